// round 2
// baseline (speedup 1.0000x reference)
#include <cuda_runtime.h>
#include <cuda_fp8.h>
#include <cuda_fp16.h>
#include <cstdint>

// Quantize_55327768707293
// x: [8192, 8192] fp32. Tiled 128x128. Per tile:
//   absmax -> e = ceil(log2(absmax)) (absmax==0 -> e=0)
//   scale = 2^(e-1)   (MAX_EXP = 1)
//   xq = fp32(fp8_e5m2(x * 2^(1-e)))
// Output: [xq (8192*8192 fp32) | scale (64*64 fp32)]
//
// R2: persistent CTAs (1/SM), 3-stage cp.async pipeline. Loads for tile t+3
// stream while tile t is reduced/quantized/stored -> continuous DRAM traffic.
// Each thread owns disjoint 16B chunks of the tile, so buffer reuse needs NO
// block barrier; only the absmax reduction barriers remain (parity-buffered).

constexpr int N        = 8192;
constexpr int B        = 128;
constexpr int TILES    = N / B;            // 64
constexpr int NTILES   = TILES * TILES;    // 4096
constexpr int THREADS  = 1024;             // 32 warps
constexpr int NWARPS   = THREADS / 32;
constexpr int STAGES   = 3;
constexpr int TILE_BYTES = B * B * 4;      // 65536
constexpr int CHUNKS   = TILE_BYTES / 16;  // 4096 x 16B
constexpr int CPT      = CHUNKS / THREADS; // 4 chunks per thread
constexpr int GRID     = 148;              // >=1 CTA/SM persistent; DRAM-bound so exact SM count is non-critical

__device__ __forceinline__ float2 fakequant2(float a, float b) {
    // fp32 -> e5m2 (RNE, hardware cvt) -> half (exact) -> fp32 (exact)
    float2 in = make_float2(a, b);
    __nv_fp8x2_storage_t q = __nv_cvt_float2_to_fp8x2(in, __NV_SATFINITE, __NV_E5M2);
    __half2_raw hr = __nv_cvt_fp8x2_to_halfraw2(q, __NV_E5M2);
    __half2 h = *reinterpret_cast<__half2*>(&hr);
    return __half22float2(h);
}

__device__ __forceinline__ void cp16(uint32_t saddr, const float* gaddr) {
    asm volatile("cp.async.cg.shared.global [%0], [%1], 16;\n"
                 :: "r"(saddr), "l"(gaddr));
}

__global__ void __launch_bounds__(THREADS, 1)
quantize_pipe_kernel(const float* __restrict__ x,
                     float* __restrict__ out,
                     float* __restrict__ scale_out) {
    extern __shared__ float4 sbuf[];   // STAGES * CHUNKS float4
    __shared__ float sred[2][NWARPS];
    __shared__ float sres[2];

    const int tid  = threadIdx.x;
    const int warp = tid >> 5;
    const int lane = tid & 31;
    const int bid  = blockIdx.x;

    const uint32_t smem_base = (uint32_t)__cvta_generic_to_shared(sbuf);

    // Per-thread chunk coords: chunk c = tid + k*THREADS, row = c>>5, col = (c&31)*4 floats.
    // Issue the 4 cp.asyncs of `tile` into `stage` (this thread's chunks only).
    auto issue_tile = [&](int tile, int stage) {
        const int ty = tile >> 6, tx = tile & 63;
        const float* gbase = x + (size_t)ty * B * N + (size_t)tx * B;
        const uint32_t sbase = smem_base + (uint32_t)stage * TILE_BYTES;
        #pragma unroll
        for (int k = 0; k < CPT; k++) {
            const int c = tid + k * THREADS;
            const int row  = c >> 5;
            const int col4 = (c & 31) << 2;
            cp16(sbase + (uint32_t)c * 16u, gbase + (size_t)row * N + col4);
        }
    };

    // ---- Prologue: prime STAGES tiles (always commit to keep group counting aligned) ----
    #pragma unroll
    for (int s = 0; s < STAGES; s++) {
        const int t = bid + s * GRID;
        if (t < NTILES) issue_tile(t, s);
        asm volatile("cp.async.commit_group;\n");
    }

    // ---- Main loop ----
    int i = 0;
    for (int tile = bid; tile < NTILES; tile += GRID, i++) {
        const int stage = i % STAGES;

        // Oldest group (this tile) complete -> my chunks are in smem.
        asm volatile("cp.async.wait_group 2;\n");

        const float4* sb = sbuf + (size_t)stage * CHUNKS;
        float4 v[CPT];
        #pragma unroll
        for (int k = 0; k < CPT; k++)
            v[k] = sb[tid + k * THREADS];

        // Local absmax (consumes v -> LDS results materialized before smem reuse below).
        float amax = 0.0f;
        #pragma unroll
        for (int k = 0; k < CPT; k++)
            amax = fmaxf(amax, fmaxf(fmaxf(fabsf(v[k].x), fabsf(v[k].y)),
                                     fmaxf(fabsf(v[k].z), fabsf(v[k].w))));

        // Refill this stage with tile t+3 (my chunks only -> no barrier needed).
        const int nxt = tile + STAGES * GRID;
        if (nxt < NTILES) issue_tile(nxt, stage);
        asm volatile("cp.async.commit_group;\n");

        // Block reduce absmax (parity buffers; 2 barriers).
        #pragma unroll
        for (int o = 16; o > 0; o >>= 1)
            amax = fmaxf(amax, __shfl_xor_sync(0xffffffffu, amax, o));
        const int p = i & 1;
        if (lane == 0) sred[p][warp] = amax;
        __syncthreads();
        if (warp == 0) {
            float m = sred[p][lane];
            #pragma unroll
            for (int o = 16; o > 0; o >>= 1)
                m = fmaxf(m, __shfl_xor_sync(0xffffffffu, m, o));
            if (lane == 0) sres[p] = m;
        }
        __syncthreads();
        const float a = sres[p];

        // e = ceil(log2(a)) exact; a==0 -> e=0.
        int e = 0;
        if (a > 0.0f) {
            int kk;
            float m = frexpf(a, &kk);       // a = m * 2^kk, m in [0.5, 1)
            e = (m == 0.5f) ? (kk - 1) : kk;
        }
        const float inv = ldexpf(1.0f, 1 - e);   // 2^(MAX_EXP - e), exact

        // Quantize from regs, store.
        const int ty = tile >> 6, tx = tile & 63;
        float* obase = out + (size_t)ty * B * N + (size_t)tx * B;
        #pragma unroll
        for (int k = 0; k < CPT; k++) {
            const int c = tid + k * THREADS;
            const int row  = c >> 5;
            const int col4 = (c & 31) << 2;
            float2 xy = fakequant2(v[k].x * inv, v[k].y * inv);
            float2 zw = fakequant2(v[k].z * inv, v[k].w * inv);
            *reinterpret_cast<float4*>(obase + (size_t)row * N + col4) =
                make_float4(xy.x, xy.y, zw.x, zw.y);
        }

        if (tid == 0) scale_out[tile] = ldexpf(1.0f, e - 1);
    }
}

extern "C" void kernel_launch(void* const* d_in, const int* in_sizes, int n_in,
                              void* d_out, int out_size) {
    (void)in_sizes; (void)n_in; (void)out_size;
    const float* x = (const float*)d_in[0];
    float* out = (float*)d_out;
    float* scale_out = out + (size_t)N * N;

    static bool attr_set = false;
    if (!attr_set) {
        cudaFuncSetAttribute(quantize_pipe_kernel,
                             cudaFuncAttributeMaxDynamicSharedMemorySize,
                             STAGES * TILE_BYTES);
        attr_set = true;
    }
    quantize_pipe_kernel<<<GRID, THREADS, STAGES * TILE_BYTES>>>(x, out, scale_out);
}

// round 3
// speedup vs baseline: 1.0083x; 1.0083x over previous
#include <cuda_runtime.h>
#include <cuda_fp8.h>
#include <cuda_fp16.h>
#include <cstdint>

// Quantize_55327768707293
// x: [8192, 8192] fp32. Tiled 128x128. Per tile:
//   absmax -> e = ceil(log2(absmax)) (absmax==0 -> e=0)
//   scale = 2^(e-1)   (MAX_EXP = 1)
//   xq = fp32(fp8_e5m2(x * 2^(1-e)))
// Output: [xq (8192*8192 fp32) | scale (64*64 fp32)]
//
// R3: persistent CTAs (1/SM, 512 thr), register double-buffer across tiles.
// Loads for tile t+1 are issued BEFORE tile t's data is consumed, keeping
// ~128KB of reads outstanding per SM so the DRAM stream never stalls on the
// per-tile reduce/store phase. No smem staging (R2's mistake) — registers only.

constexpr int N        = 8192;
constexpr int B        = 128;
constexpr int TILES    = N / B;            // 64
constexpr int NTILES   = TILES * TILES;    // 4096
constexpr int THREADS  = 512;              // 16 warps
constexpr int NWARPS   = THREADS / 32;
constexpr int SWEEPS   = 8;                // float4 per thread (32 floats)
constexpr int GRID     = 148;              // persistent, 1 CTA/SM
constexpr int ROW4     = N / 4;            // row stride in float4

__device__ __forceinline__ float2 fakequant2(float a, float b) {
    // fp32 -> e5m2 (RNE, hardware cvt) -> half (exact) -> fp32 (exact)
    float2 in = make_float2(a, b);
    __nv_fp8x2_storage_t q = __nv_cvt_float2_to_fp8x2(in, __NV_SATFINITE, __NV_E5M2);
    __half2_raw hr = __nv_cvt_fp8x2_to_halfraw2(q, __NV_E5M2);
    __half2 h = *reinterpret_cast<__half2*>(&hr);
    return __half22float2(h);
}

__device__ __forceinline__ void load_tile(const float* __restrict__ x, int tile,
                                          float4 (&v)[SWEEPS], int warp, int lane) {
    const int ty = tile >> 6, tx = tile & 63;
    const float4* __restrict__ p =
        reinterpret_cast<const float4*>(x + (size_t)ty * B * N + (size_t)tx * B);
    #pragma unroll
    for (int i = 0; i < SWEEPS; i++) {
        const int row = warp + i * NWARPS;
        v[i] = __ldcs(&p[(size_t)row * ROW4 + lane]);
    }
}

struct Ctx {
    const float* __restrict__ x;
    float* __restrict__ out;
    float* __restrict__ scale_out;
    float* sred;   // [NWARPS]
    float* sres;   // [1]
    int tid, warp, lane;
};

// Process tile t held in `cur`; prefetch tile nt into `nxt` first.
__device__ __forceinline__ void process(const Ctx& c, int t,
                                        float4 (&cur)[SWEEPS],
                                        int nt, float4 (&nxt)[SWEEPS]) {
    // Prefetch next tile before consuming current (keeps DRAM stream going).
    if (nt < NTILES) load_tile(c.x, nt, nxt, c.warp, c.lane);

    // Local absmax (first consumption of cur -> waits on cur's LDGs).
    float amax = 0.0f;
    #pragma unroll
    for (int i = 0; i < SWEEPS; i++)
        amax = fmaxf(amax, fmaxf(fmaxf(fabsf(cur[i].x), fabsf(cur[i].y)),
                                 fmaxf(fabsf(cur[i].z), fabsf(cur[i].w))));

    // Block reduce (2 barriers).
    #pragma unroll
    for (int o = 16; o > 0; o >>= 1)
        amax = fmaxf(amax, __shfl_xor_sync(0xffffffffu, amax, o));
    if (c.lane == 0) c.sred[c.warp] = amax;
    __syncthreads();
    if (c.warp == 0) {
        float m = (c.lane < NWARPS) ? c.sred[c.lane] : 0.0f;
        #pragma unroll
        for (int o = 8; o > 0; o >>= 1)
            m = fmaxf(m, __shfl_xor_sync(0xffffffffu, m, o));
        if (c.lane == 0) c.sres[0] = m;
    }
    __syncthreads();
    const float a = c.sres[0];

    // e = ceil(log2(a)) exact; a==0 -> e=0.
    int e = 0;
    if (a > 0.0f) {
        int k;
        float m = frexpf(a, &k);          // a = m * 2^k, m in [0.5, 1)
        e = (m == 0.5f) ? (k - 1) : k;
    }
    const float inv = ldexpf(1.0f, 1 - e);    // 2^(MAX_EXP - e), exact

    // Quantize from regs, streaming stores.
    const int ty = t >> 6, tx = t & 63;
    float4* __restrict__ oq =
        reinterpret_cast<float4*>(c.out + (size_t)ty * B * N + (size_t)tx * B);
    #pragma unroll
    for (int i = 0; i < SWEEPS; i++) {
        const int row = c.warp + i * NWARPS;
        float2 xy = fakequant2(cur[i].x * inv, cur[i].y * inv);
        float2 zw = fakequant2(cur[i].z * inv, cur[i].w * inv);
        __stcs(&oq[(size_t)row * ROW4 + c.lane],
               make_float4(xy.x, xy.y, zw.x, zw.y));
    }

    if (c.tid == 0) c.scale_out[t] = ldexpf(1.0f, e - 1);
}

__global__ void __launch_bounds__(THREADS, 1)
quantize_rpipe_kernel(const float* __restrict__ x,
                      float* __restrict__ out,
                      float* __restrict__ scale_out) {
    __shared__ float sred[NWARPS];
    __shared__ float sres[1];

    Ctx c{x, out, scale_out, sred, sres,
          (int)threadIdx.x, (int)threadIdx.x >> 5, (int)threadIdx.x & 31};

    float4 bufA[SWEEPS], bufB[SWEEPS];

    int t = blockIdx.x;                       // < 148 <= NTILES always
    load_tile(x, t, bufA, c.warp, c.lane);

    while (true) {
        int t2 = t + GRID;
        process(c, t, bufA, t2, bufB);        // prefetches t2 into B
        if (t2 >= NTILES) break;
        t = t2;
        t2 = t + GRID;
        process(c, t, bufB, t2, bufA);        // prefetches t2 into A
        if (t2 >= NTILES) break;
        t = t2;
    }
}

extern "C" void kernel_launch(void* const* d_in, const int* in_sizes, int n_in,
                              void* d_out, int out_size) {
    (void)in_sizes; (void)n_in; (void)out_size;
    const float* x = (const float*)d_in[0];
    float* out = (float*)d_out;
    float* scale_out = out + (size_t)N * N;

    quantize_rpipe_kernel<<<GRID, THREADS>>>(x, out, scale_out);
}

// round 5
// speedup vs baseline: 1.0261x; 1.0177x over previous
#include <cuda_runtime.h>
#include <cuda_fp8.h>
#include <cuda_fp16.h>
#include <cstdint>

// Quantize_55327768707293
// x: [8192, 8192] fp32. Tiled 128x128. Per tile:
//   absmax -> e = ceil(log2(absmax)) (absmax==0 -> e=0)
//   scale = 2^(e-1)   (MAX_EXP = 1)
//   xq = fp32(fp8_e5m2(x * 2^(1-e)))
// Output: [xq (8192*8192 fp32) | scale (64*64 fp32)]
//
// R5: two-phase, high-occupancy (R4 intent, compilable intrinsics).
// Phase A: stream tile through L2 (__ldcg) computing absmax.
// Phase B: re-read tile (L2 hit, __ldcs last-use), quantize, __stcs stores.
// 256-thread CTAs, ~6 CTAs/SM -> many phase-shifted CTAs keep DRAM saturated;
// concurrent working set ~57MB << 126MB L2 so phase-B reads hit L2.

constexpr int N        = 8192;
constexpr int B        = 128;
constexpr int TILES    = N / B;            // 64
constexpr int THREADS  = 256;              // 8 warps
constexpr int NWARPS   = THREADS / 32;
constexpr int CHUNKS   = B * B / 4;        // 4096 float4 per tile
constexpr int CPT      = CHUNKS / THREADS; // 16 float4 per thread
constexpr int ROW4     = N / 4;

__device__ __forceinline__ float2 fakequant2(float a, float b) {
    // fp32 -> e5m2 (RNE, hardware cvt) -> half (exact) -> fp32 (exact)
    float2 in = make_float2(a, b);
    __nv_fp8x2_storage_t q = __nv_cvt_float2_to_fp8x2(in, __NV_SATFINITE, __NV_E5M2);
    __half2_raw hr = __nv_cvt_fp8x2_to_halfraw2(q, __NV_E5M2);
    __half2 h = *reinterpret_cast<__half2*>(&hr);
    return __half22float2(h);
}

__global__ void __launch_bounds__(THREADS, 6)
quantize_twophase_kernel(const float* __restrict__ x,
                         float* __restrict__ out,
                         float* __restrict__ scale_out) {
    __shared__ float sred[NWARPS];
    __shared__ float sres;

    const int tid  = threadIdx.x;
    const int warp = tid >> 5;
    const int lane = tid & 31;

    const int t  = blockIdx.x;            // one tile per CTA
    const int ty = t >> 6, tx = t & 63;
    const size_t base = (size_t)ty * B * N + (size_t)tx * B;
    const float4* __restrict__ p4 = reinterpret_cast<const float4*>(x + base);
    float4* __restrict__ o4       = reinterpret_cast<float4*>(out + base);

    // ---- Phase A: absmax over this thread's 16 chunks (L2-cached reads) ----
    float amax = 0.0f;
    #pragma unroll
    for (int k = 0; k < CPT; k++) {
        const int c   = tid + k * THREADS;     // contiguous within warp -> coalesced
        const int row = c >> 5;
        const int col = c & 31;
        float4 v = __ldcg(&p4[(size_t)row * ROW4 + col]);
        amax = fmaxf(amax, fmaxf(fmaxf(fabsf(v.x), fabsf(v.y)),
                                 fmaxf(fabsf(v.z), fabsf(v.w))));
    }

    // ---- Block reduce ----
    #pragma unroll
    for (int o = 16; o > 0; o >>= 1)
        amax = fmaxf(amax, __shfl_xor_sync(0xffffffffu, amax, o));
    if (lane == 0) sred[warp] = amax;
    __syncthreads();
    if (warp == 0) {
        float m = (lane < NWARPS) ? sred[lane] : 0.0f;
        #pragma unroll
        for (int o = 4; o > 0; o >>= 1)
            m = fmaxf(m, __shfl_xor_sync(0xffffffffu, m, o));
        if (lane == 0) sres = m;
    }
    __syncthreads();
    const float a = sres;

    // ---- e = ceil(log2(a)) exact; a==0 -> e=0 ----
    int e = 0;
    if (a > 0.0f) {
        int k;
        float m = frexpf(a, &k);          // a = m * 2^k, m in [0.5, 1)
        e = (m == 0.5f) ? (k - 1) : k;
    }
    const float inv = ldexpf(1.0f, 1 - e);    // 2^(MAX_EXP - e), exact

    // ---- Phase B: re-read (L2 hit, last-use), quantize, streaming stores ----
    #pragma unroll
    for (int k = 0; k < CPT; k++) {
        const int c   = tid + k * THREADS;
        const int row = c >> 5;
        const int col = c & 31;
        const size_t off = (size_t)row * ROW4 + col;
        float4 v = __ldcs(&p4[off]);
        float2 xy = fakequant2(v.x * inv, v.y * inv);
        float2 zw = fakequant2(v.z * inv, v.w * inv);
        __stcs(&o4[off], make_float4(xy.x, xy.y, zw.x, zw.y));
    }

    if (tid == 0) scale_out[t] = ldexpf(1.0f, e - 1);
}

extern "C" void kernel_launch(void* const* d_in, const int* in_sizes, int n_in,
                              void* d_out, int out_size) {
    (void)in_sizes; (void)n_in; (void)out_size;
    const float* x = (const float*)d_in[0];
    float* out = (float*)d_out;
    float* scale_out = out + (size_t)N * N;

    quantize_twophase_kernel<<<TILES * TILES, THREADS>>>(x, out, scale_out);
}

// round 6
// speedup vs baseline: 1.1063x; 1.0781x over previous
#include <cuda_runtime.h>
#include <cuda_fp8.h>
#include <cuda_fp16.h>
#include <cstdint>

// Quantize_55327768707293
// x: [8192, 8192] fp32. Tiled 128x128. Per tile:
//   absmax -> e = ceil(log2(absmax)) (absmax==0 -> e=0)
//   scale = 2^(e-1)   (MAX_EXP = 1)
//   xq = fp32(fp8_e5m2(x * 2^(1-e)))
// Output: [xq (8192*8192 fp32) | scale (64*64 fp32)]
//
// R6: R1 structure (register-staged tile, one CTA per tile) but 3 CTAs/SM
// (launch_bounds(512,3) -> <=42 regs). Three independently-phased sync
// domains per SM: while one CTA sits in its reduce/store phase, two others
// stream loads -> smoother DRAM utilization. Streaming ld/st hints (data is
// touched exactly once; skip L1 allocation).

constexpr int N        = 8192;
constexpr int B        = 128;
constexpr int TILES    = N / B;          // 64
constexpr int THREADS  = 512;            // 16 warps
constexpr int NWARPS   = THREADS / 32;
constexpr int SWEEPS   = B / NWARPS;     // 8 float4 per thread (32 floats)
constexpr int ROW4     = N / 4;

__device__ __forceinline__ float2 fakequant2(float a, float b) {
    // fp32 -> e5m2 (RNE, hardware cvt) -> half (exact) -> fp32 (exact)
    float2 in = make_float2(a, b);
    __nv_fp8x2_storage_t q = __nv_cvt_float2_to_fp8x2(in, __NV_SATFINITE, __NV_E5M2);
    __half2_raw hr = __nv_cvt_fp8x2_to_halfraw2(q, __NV_E5M2);
    __half2 h = *reinterpret_cast<__half2*>(&hr);
    return __half22float2(h);
}

__global__ void __launch_bounds__(THREADS, 3)
quantize_tile_kernel(const float* __restrict__ x,
                     float* __restrict__ out,
                     float* __restrict__ scale_out) {
    const int tx   = blockIdx.x;          // tile col
    const int ty   = blockIdx.y;          // tile row
    const int warp = threadIdx.x >> 5;
    const int lane = threadIdx.x & 31;

    const size_t tile_base = (size_t)ty * B * N + (size_t)tx * B;
    const float4* __restrict__ xin = reinterpret_cast<const float4*>(x + tile_base);
    float4* __restrict__ oq        = reinterpret_cast<float4*>(out + tile_base);

    // ---- Load whole tile into registers; front-batched LDG.128 for MLP ----
    float4 v[SWEEPS];
    #pragma unroll
    for (int i = 0; i < SWEEPS; i++) {
        const int row = warp + i * NWARPS;
        v[i] = __ldcs(&xin[(size_t)row * ROW4 + lane]);
    }

    // ---- Local absmax ----
    float amax = 0.0f;
    #pragma unroll
    for (int i = 0; i < SWEEPS; i++) {
        amax = fmaxf(amax, fmaxf(fmaxf(fabsf(v[i].x), fabsf(v[i].y)),
                                 fmaxf(fabsf(v[i].z), fabsf(v[i].w))));
    }

    // ---- Block reduce absmax ----
    #pragma unroll
    for (int o = 16; o > 0; o >>= 1)
        amax = fmaxf(amax, __shfl_xor_sync(0xffffffffu, amax, o));

    __shared__ float smax[NWARPS];
    if (lane == 0) smax[warp] = amax;
    __syncthreads();
    if (warp == 0) {
        float m = (lane < NWARPS) ? smax[lane] : 0.0f;
        #pragma unroll
        for (int o = 8; o > 0; o >>= 1)
            m = fmaxf(m, __shfl_xor_sync(0xffffffffu, m, o));
        if (lane == 0) smax[0] = m;
    }
    __syncthreads();
    const float a = smax[0];

    // ---- e = ceil(log2(a)), exact; a==0 -> e=0 ----
    int e = 0;
    if (a > 0.0f) {
        int k;
        float m = frexpf(a, &k);          // a = m * 2^k, m in [0.5, 1)
        e = (m == 0.5f) ? (k - 1) : k;    // exact power of two -> k-1
    }
    const float inv = ldexpf(1.0f, 1 - e);    // 2^(MAX_EXP - e), exact

    // ---- Quantize from registers, streaming stores ----
    #pragma unroll
    for (int i = 0; i < SWEEPS; i++) {
        const int row = warp + i * NWARPS;
        float2 xy = fakequant2(v[i].x * inv, v[i].y * inv);
        float2 zw = fakequant2(v[i].z * inv, v[i].w * inv);
        __stcs(&oq[(size_t)row * ROW4 + lane],
               make_float4(xy.x, xy.y, zw.x, zw.y));
    }

    if (threadIdx.x == 0)
        scale_out[ty * TILES + tx] = ldexpf(1.0f, e - 1);
}

extern "C" void kernel_launch(void* const* d_in, const int* in_sizes, int n_in,
                              void* d_out, int out_size) {
    (void)in_sizes; (void)n_in; (void)out_size;
    const float* x = (const float*)d_in[0];
    float* out = (float*)d_out;
    float* scale_out = out + (size_t)N * N;

    dim3 grid(TILES, TILES);
    quantize_tile_kernel<<<grid, THREADS>>>(x, out, scale_out);
}